// round 6
// baseline (speedup 1.0000x reference)
#include <cuda_runtime.h>
#include <math.h>

#define NUM_RADIUS 15
#define NUM_ANGLE 48
#define EMB 32
#define NUM_ACTIONS 4
#define NUM_COMBO (NUM_RADIUS * NUM_ANGLE)   // 720
#define TPB 256

// Bucket-pair index. Reuses radius (=hypot) for the atan2 half-angle
// reduction: u = mn/(mx + hypot) = t/(1+sqrt(1+t^2)), u in [0, 0.4142].
// Taylor atan(u) through u^13: truncation <= u^15/15 ~ 1.2e-7 rad.
__device__ __forceinline__ int bucket_index(float axp, float azp, float pose,
                                            float gx, float gz) {
    float dx = gx - axp;
    float dz = gz - azp;

    float radius = sqrtf(fmaf(dx, dx, dz * dz));
    int r_idx = min((int)(radius * 0.2f), NUM_RADIUS - 1);

    float ax = fabsf(dx), ay = fabsf(dz);
    float mn = fminf(ax, ay), mx = fmaxf(ax, ay);
    float u = __fdividef(mn, mx + radius);
    float s = u * u;
    float p = 0.07692307693f;                 //  1/13
    p = fmaf(p, s, -0.09090909091f);          // -1/11
    p = fmaf(p, s,  0.11111111111f);          //  1/9
    p = fmaf(p, s, -0.14285714286f);          // -1/7
    p = fmaf(p, s,  0.2f);                    //  1/5
    p = fmaf(p, s, -0.33333333333f);          // -1/3
    float atu = fmaf(p * s, u, u);            // atan(u)
    float a = 2.0f * atu;                     // atan(mn/mx)
    if (ay > ax) a = 1.57079632679f - a;
    if (dx < 0.0f) a = 3.14159265359f - a;
    a = (dz < 0.0f) ? -a : a;                 // atan2(dz, dx)

    float deg = __fmul_rn(a, 57.29577951308232f);
    float dtg = __fsub_rn(90.0f, deg);
    float f = __fsub_rn(dtg, pose);
    float ad = fmaf(-360.0f, floorf(f * 0.0027777778f), f);
    ad = fminf(fmaxf(ad, 0.0f), 359.99997f);
    int t_idx = (int)(ad * 0.13333334f);      // in [0,47] by construction

    return r_idx * NUM_ANGLE + t_idx;
}

__global__ void __launch_bounds__(TPB)
goal_position_fused(const float4* __restrict__ agent4,  // [B,3] as float4s
                    const float4* __restrict__ goal4,   // [B,2] as float4s
                    float4* __restrict__ out,           // [B,4]
                    int n4,                              // B/4
                    const float* __restrict__ radius_table,
                    const float* __restrict__ angle_table,
                    const float* __restrict__ W,
                    const float* __restrict__ b) {
    __shared__ float  sW[2 * EMB * NUM_ACTIONS];   // 256 floats
    __shared__ float  sLR[NUM_RADIUS * NUM_ACTIONS];   // 60
    __shared__ float  sLA[NUM_ANGLE * NUM_ACTIONS];    // 192
    __shared__ float4 sLS[NUM_COMBO];              // 11.25 KB
    __shared__ float4 sAg[3 * TPB];                // 12 KB agent slab

    const int t = threadIdx.x;

    // ---- Prologue: build the 720-entry output table in this block ----
    if (t < 2 * EMB * NUM_ACTIONS) sW[t] = W[t];
    __syncthreads();

    if (t < NUM_RADIUS * NUM_ACTIONS) {                 // 60 dots
        int row = t >> 2, a = t & 3;
        float s = 0.0f;
        #pragma unroll
        for (int e = 0; e < EMB; e++)
            s += __ldg(&radius_table[row * EMB + e]) * sW[e * NUM_ACTIONS + a];
        sLR[t] = s;
    } else if (t < (NUM_RADIUS + NUM_ANGLE) * NUM_ACTIONS) {  // 192 dots
        int k = t - NUM_RADIUS * NUM_ACTIONS;
        int row = k >> 2, a = k & 3;
        float s = __ldg(&b[a]);
        #pragma unroll
        for (int e = 0; e < EMB; e++)
            s += __ldg(&angle_table[row * EMB + e]) * sW[(EMB + e) * NUM_ACTIONS + a];
        sLA[k] = s;
    }
    __syncthreads();

    for (int c = t; c < NUM_COMBO; c += TPB) {
        int r = c / NUM_ANGLE;
        int ta = c - r * NUM_ANGLE;
        float l0 = sLR[r * 4 + 0] + sLA[ta * 4 + 0];
        float l1 = sLR[r * 4 + 1] + sLA[ta * 4 + 1];
        float l2 = sLR[r * 4 + 2] + sLA[ta * 4 + 2];
        float l3 = sLR[r * 4 + 3] + sLA[ta * 4 + 3];
        float m = fmaxf(fmaxf(l0, l1), fmaxf(l2, l3));
        float e0 = __expf(l0 - m), e1 = __expf(l1 - m);
        float e2 = __expf(l2 - m), e3 = __expf(l3 - m);
        float lse = __logf(e0 + e1 + e2 + e3) + m;
        sLS[c] = make_float4(l0 - lse, l1 - lse, l2 - lse, l3 - lse);
    }
    __syncthreads();

    // ---- Main loop: tiles of TPB threads x 4 rows, grid-stride ----
    for (int base = blockIdx.x * TPB; base < n4; base += gridDim.x * TPB) {
        // Stage this tile's agent slab with perfectly coalesced loads:
        // region agent4[3*base .. 3*(base+tile)). 3 float4 per thread.
        int tile = min(TPB, n4 - base);
        int cnt = 3 * tile;
        const float4* src = agent4 + 3 * base;
        #pragma unroll
        for (int k = 0; k < 3; k++) {
            int idx = t + k * TPB;
            if (idx < cnt) sAg[idx] = src[idx];
        }
        __syncthreads();

        int i = base + t;
        if (i < n4) {
            // Conflict-free per 8-lane phase (stride 12 words -> distinct banks)
            float4 a0 = sAg[3 * t + 0];   // x0 z0 p0 x1
            float4 a1 = sAg[3 * t + 1];   // z1 p1 x2 z2
            float4 a2 = sAg[3 * t + 2];   // p2 x3 z3 p3
            float4 g0 = goal4[2 * i + 0]; // gx0 gz0 gx1 gz1
            float4 g1 = goal4[2 * i + 1]; // gx2 gz2 gx3 gz3

            int c0 = bucket_index(a0.x, a0.y, a0.z, g0.x, g0.y);
            int c1 = bucket_index(a0.w, a1.x, a1.y, g0.z, g0.w);
            int c2 = bucket_index(a1.z, a1.w, a2.x, g1.x, g1.y);
            int c3 = bucket_index(a2.y, a2.z, a2.w, g1.z, g1.w);

            out[4 * i + 0] = sLS[c0];
            out[4 * i + 1] = sLS[c1];
            out[4 * i + 2] = sLS[c2];
            out[4 * i + 3] = sLS[c3];
        }
        __syncthreads();   // protect sAg before next tile overwrites
    }
}

extern "C" void kernel_launch(void* const* d_in, const int* in_sizes, int n_in,
                              void* d_out, int out_size) {
    const float* agent = (const float*)d_in[0];   // [B,3]
    const float* goal = (const float*)d_in[1];    // [B,2]
    const float* radius_table = (const float*)d_in[2];
    const float* angle_table = (const float*)d_in[3];
    const float* W = (const float*)d_in[4];
    const float* b = (const float*)d_in[5];

    int n = in_sizes[0] / 3;    // B = 2,000,000 (divisible by 4)
    int n4 = n / 4;

    // 8 blocks/SM x 148 SMs, full occupancy, ~1.65 grid-stride iterations.
    int blocks = 148 * 8;
    int max_blocks = (n4 + TPB - 1) / TPB;
    if (blocks > max_blocks) blocks = max_blocks;

    goal_position_fused<<<blocks, TPB>>>((const float4*)agent,
                                         (const float4*)goal,
                                         (float4*)d_out, n4,
                                         radius_table, angle_table, W, b);
}

// round 7
// speedup vs baseline: 1.1569x; 1.1569x over previous
#include <cuda_runtime.h>
#include <math.h>

#define NUM_RADIUS 15
#define NUM_ANGLE 48
#define EMB 32
#define NUM_ACTIONS 4
#define NUM_COMBO (NUM_RADIUS * NUM_ANGLE)   // 720
#define TPB 256

// Bucket-pair index. Reuses radius (=hypot) for the atan2 half-angle
// reduction: u = mn/(mx + hypot) = t/(1+sqrt(1+t^2)), u in [0, 0.4142].
// Taylor atan(u) through u^13: truncation <= u^15/15 ~ 1.2e-7 rad.
__device__ __forceinline__ int bucket_index(float axp, float azp, float pose,
                                            float gx, float gz) {
    float dx = gx - axp;
    float dz = gz - azp;

    float radius = sqrtf(fmaf(dx, dx, dz * dz));
    int r_idx = min((int)(radius * 0.2f), NUM_RADIUS - 1);

    float ax = fabsf(dx), ay = fabsf(dz);
    float mn = fminf(ax, ay), mx = fmaxf(ax, ay);
    float u = __fdividef(mn, mx + radius);
    float s = u * u;
    float p = 0.07692307693f;                 //  1/13
    p = fmaf(p, s, -0.09090909091f);          // -1/11
    p = fmaf(p, s,  0.11111111111f);          //  1/9
    p = fmaf(p, s, -0.14285714286f);          // -1/7
    p = fmaf(p, s,  0.2f);                    //  1/5
    p = fmaf(p, s, -0.33333333333f);          // -1/3
    float atu = fmaf(p * s, u, u);            // atan(u)
    float a = 2.0f * atu;                     // atan(mn/mx)
    if (ay > ax) a = 1.57079632679f - a;
    if (dx < 0.0f) a = 3.14159265359f - a;
    a = (dz < 0.0f) ? -a : a;                 // atan2(dz, dx)

    float deg = __fmul_rn(a, 57.29577951308232f);
    float dtg = __fsub_rn(90.0f, deg);
    float f = __fsub_rn(dtg, pose);
    float ad = fmaf(-360.0f, floorf(f * 0.0027777778f), f);
    ad = fminf(fmaxf(ad, 0.0f), 359.99997f);
    int t_idx = (int)(ad * 0.13333334f);      // in [0,47] by construction

    return r_idx * NUM_ANGLE + t_idx;
}

__global__ void __launch_bounds__(TPB)
goal_position_fused(const float* __restrict__ agentF,   // [B*3] floats
                    const float2* __restrict__ goal2,   // [B] float2
                    float4* __restrict__ out,           // [B] float4
                    int n,                               // B rows
                    const float* __restrict__ radius_table,
                    const float* __restrict__ angle_table,
                    const float* __restrict__ W,
                    const float* __restrict__ b) {
    __shared__ float  sW[2 * EMB * NUM_ACTIONS];       // 256 floats
    __shared__ float  sLR[NUM_RADIUS * NUM_ACTIONS];   // 60
    __shared__ float  sLA[NUM_ANGLE * NUM_ACTIONS];    // 192
    __shared__ float4 sLS[NUM_COMBO];                  // 11.25 KB

    const int t = threadIdx.x;
    const int lane = t & 31;
    const int warp = t >> 5;

    // ---- Prologue: build the 720-entry log-softmax table (once per block;
    // all blocks do this concurrently at launch, ~0.5us wall) ----
    if (t < 2 * EMB * NUM_ACTIONS) sW[t] = W[t];
    __syncthreads();

    if (t < NUM_RADIUS * NUM_ACTIONS) {                 // 60 dots
        int row = t >> 2, a = t & 3;
        float s = 0.0f;
        #pragma unroll
        for (int e = 0; e < EMB; e++)
            s += __ldg(&radius_table[row * EMB + e]) * sW[e * NUM_ACTIONS + a];
        sLR[t] = s;
    } else if (t < (NUM_RADIUS + NUM_ANGLE) * NUM_ACTIONS) {  // 192 dots
        int k = t - NUM_RADIUS * NUM_ACTIONS;
        int row = k >> 2, a = k & 3;
        float s = __ldg(&b[a]);
        #pragma unroll
        for (int e = 0; e < EMB; e++)
            s += __ldg(&angle_table[row * EMB + e]) * sW[(EMB + e) * NUM_ACTIONS + a];
        sLA[k] = s;
    }
    __syncthreads();

    for (int c = t; c < NUM_COMBO; c += TPB) {
        int r = c / NUM_ANGLE;
        int ta = c - r * NUM_ANGLE;
        float l0 = sLR[r * 4 + 0] + sLA[ta * 4 + 0];
        float l1 = sLR[r * 4 + 1] + sLA[ta * 4 + 1];
        float l2 = sLR[r * 4 + 2] + sLA[ta * 4 + 2];
        float l3 = sLR[r * 4 + 3] + sLA[ta * 4 + 3];
        float m = fmaxf(fmaxf(l0, l1), fmaxf(l2, l3));
        float e0 = __expf(l0 - m), e1 = __expf(l1 - m);
        float e2 = __expf(l2 - m), e3 = __expf(l3 - m);
        float lse = __logf(e0 + e1 + e2 + e3) + m;
        sLS[c] = make_float4(l0 - lse, l1 - lse, l2 - lse, l3 - lse);
    }
    __syncthreads();

    // ---- Main loop: 1 row/thread; agent loaded fully coalesced (3x LDG.32,
    // 1 line each) and redistributed via warp shuffle (no L1 traffic).
    // NO barriers, NO smem writes in the loop. All 32 lanes stay active.
    const int n3 = 3 * n;
    const int stride = gridDim.x * TPB;
    for (int base = blockIdx.x * TPB; base < n; base += stride) {
        int row = base + t;                     // this thread's row (may be >= n)
        int slab = 3 * base + 96 * warp;        // warp's 96-float agent slab

        // Coalesced slab loads (guard only the global index, lanes all active)
        int i0 = slab + lane;
        int i1 = i0 + 32;
        int i2 = i0 + 64;
        float v0 = (i0 < n3) ? agentF[i0] : 0.0f;
        float v1 = (i1 < n3) ? agentF[i1] : 0.0f;
        float v2 = (i2 < n3) ? agentF[i2] : 0.0f;
        float2 g = (row < n) ? goal2[row] : make_float2(0.0f, 0.0f);

        // Warp transpose: lane L needs slab floats 3L, 3L+1, 3L+2
        int g0i = 3 * lane, g1i = g0i + 1, g2i = g0i + 2;
        float x, z, pz;
        {
            float s0 = __shfl_sync(0xffffffffu, v0, g0i & 31);
            float s1 = __shfl_sync(0xffffffffu, v1, g0i & 31);
            float s2 = __shfl_sync(0xffffffffu, v2, g0i & 31);
            int r0 = g0i >> 5;
            x = (r0 == 0) ? s0 : ((r0 == 1) ? s1 : s2);
        }
        {
            float s0 = __shfl_sync(0xffffffffu, v0, g1i & 31);
            float s1 = __shfl_sync(0xffffffffu, v1, g1i & 31);
            float s2 = __shfl_sync(0xffffffffu, v2, g1i & 31);
            int r1 = g1i >> 5;
            z = (r1 == 0) ? s0 : ((r1 == 1) ? s1 : s2);
        }
        {
            float s0 = __shfl_sync(0xffffffffu, v0, g2i & 31);
            float s1 = __shfl_sync(0xffffffffu, v1, g2i & 31);
            float s2 = __shfl_sync(0xffffffffu, v2, g2i & 31);
            int r2 = g2i >> 5;
            pz = (r2 == 0) ? s0 : ((r2 == 1) ? s1 : s2);
        }

        if (row < n) {
            int c = bucket_index(x, z, pz, g.x, g.y);
            out[row] = sLS[c];
        }
    }
}

extern "C" void kernel_launch(void* const* d_in, const int* in_sizes, int n_in,
                              void* d_out, int out_size) {
    const float* agent = (const float*)d_in[0];   // [B,3]
    const float* goal = (const float*)d_in[1];    // [B,2]
    const float* radius_table = (const float*)d_in[2];
    const float* angle_table = (const float*)d_in[3];
    const float* W = (const float*)d_in[4];
    const float* b = (const float*)d_in[5];

    int n = in_sizes[0] / 3;    // B = 2,000,000

    int tiles = (n + TPB - 1) / TPB;
    int blocks = 148 * 8;
    if (blocks > tiles) blocks = tiles;

    goal_position_fused<<<blocks, TPB>>>(agent,
                                         (const float2*)goal,
                                         (float4*)d_out, n,
                                         radius_table, angle_table, W, b);
}

// round 8
// speedup vs baseline: 1.2459x; 1.0769x over previous
#include <cuda_runtime.h>
#include <math.h>

#define NUM_RADIUS 15
#define NUM_ANGLE 48
#define EMB 32
#define NUM_ACTIONS 4
#define NUM_COMBO (NUM_RADIUS * NUM_ANGLE)   // 720
#define TPB 256

// Bucket-pair index. Reuses radius (=hypot) for the atan2 half-angle
// reduction: u = mn/(mx + hypot) = t/(1+sqrt(1+t^2)), u in [0, 0.4142].
// Taylor atan(u) through u^13: truncation <= u^15/15 ~ 1.2e-7 rad.
__device__ __forceinline__ int bucket_index(float axp, float azp, float pose,
                                            float gx, float gz) {
    float dx = gx - axp;
    float dz = gz - azp;

    float radius = sqrtf(fmaf(dx, dx, dz * dz));
    int r_idx = min((int)(radius * 0.2f), NUM_RADIUS - 1);

    float ax = fabsf(dx), ay = fabsf(dz);
    float mn = fminf(ax, ay), mx = fmaxf(ax, ay);
    float u = __fdividef(mn, mx + radius);
    float s = u * u;
    float p = 0.07692307693f;                 //  1/13
    p = fmaf(p, s, -0.09090909091f);          // -1/11
    p = fmaf(p, s,  0.11111111111f);          //  1/9
    p = fmaf(p, s, -0.14285714286f);          // -1/7
    p = fmaf(p, s,  0.2f);                    //  1/5
    p = fmaf(p, s, -0.33333333333f);          // -1/3
    float atu = fmaf(p * s, u, u);            // atan(u)
    float a = 2.0f * atu;                     // atan(mn/mx)
    if (ay > ax) a = 1.57079632679f - a;
    if (dx < 0.0f) a = 3.14159265359f - a;
    a = (dz < 0.0f) ? -a : a;                 // atan2(dz, dx)

    float deg = __fmul_rn(a, 57.29577951308232f);
    float dtg = __fsub_rn(90.0f, deg);
    float f = __fsub_rn(dtg, pose);
    float ad = fmaf(-360.0f, floorf(f * 0.0027777778f), f);
    ad = fminf(fmaxf(ad, 0.0f), 359.99997f);
    int t_idx = (int)(ad * 0.13333334f);      // in [0,47] by construction

    return r_idx * NUM_ANGLE + t_idx;
}

__global__ void __launch_bounds__(TPB)
goal_position_fused(const float* __restrict__ agentF,   // [B*3] floats
                    const float2* __restrict__ goal2,   // [B] float2
                    float4* __restrict__ out,           // [B] float4
                    int n,                               // B rows
                    const float* __restrict__ radius_table,
                    const float* __restrict__ angle_table,
                    const float* __restrict__ W,
                    const float* __restrict__ b) {
    __shared__ float  sW[2 * EMB * NUM_ACTIONS];       // 256 floats
    __shared__ float  sLR[NUM_RADIUS * NUM_ACTIONS];   // 60
    __shared__ float  sLA[NUM_ANGLE * NUM_ACTIONS];    // 192
    __shared__ float4 sLS[NUM_COMBO];                  // 11.25 KB

    const int t = threadIdx.x;

    // ---- Prologue: build the 720-entry log-softmax table (once per block;
    // all blocks run this concurrently at launch) ----
    if (t < 2 * EMB * NUM_ACTIONS) sW[t] = W[t];
    __syncthreads();

    if (t < NUM_RADIUS * NUM_ACTIONS) {                 // 60 dots
        int row = t >> 2, a = t & 3;
        float s = 0.0f;
        #pragma unroll
        for (int e = 0; e < EMB; e++)
            s += __ldg(&radius_table[row * EMB + e]) * sW[e * NUM_ACTIONS + a];
        sLR[t] = s;
    } else if (t < (NUM_RADIUS + NUM_ANGLE) * NUM_ACTIONS) {  // 192 dots
        int k = t - NUM_RADIUS * NUM_ACTIONS;
        int row = k >> 2, a = k & 3;
        float s = __ldg(&b[a]);
        #pragma unroll
        for (int e = 0; e < EMB; e++)
            s += __ldg(&angle_table[row * EMB + e]) * sW[(EMB + e) * NUM_ACTIONS + a];
        sLA[k] = s;
    }
    __syncthreads();

    for (int c = t; c < NUM_COMBO; c += TPB) {
        int r = c / NUM_ANGLE;
        int ta = c - r * NUM_ANGLE;
        float l0 = sLR[r * 4 + 0] + sLA[ta * 4 + 0];
        float l1 = sLR[r * 4 + 1] + sLA[ta * 4 + 1];
        float l2 = sLR[r * 4 + 2] + sLA[ta * 4 + 2];
        float l3 = sLR[r * 4 + 3] + sLA[ta * 4 + 3];
        float m = fmaxf(fmaxf(l0, l1), fmaxf(l2, l3));
        float e0 = __expf(l0 - m), e1 = __expf(l1 - m);
        float e2 = __expf(l2 - m), e3 = __expf(l3 - m);
        float lse = __logf(e0 + e1 + e2 + e3) + m;
        sLS[c] = make_float4(l0 - lse, l1 - lse, l2 - lse, l3 - lse);
    }
    __syncthreads();

    // ---- Main loop: 1 row/thread, scalar agent loads (3 LDG.32, each
    // spanning only 3 lines per warp), goal LDG.64, one LDS.128 table
    // gather, one STG.128. No barriers, no smem writes, no shuffles.
    const int stride = gridDim.x * TPB;
    for (int row = blockIdx.x * TPB + t; row < n; row += stride) {
        float x  = agentF[3 * row + 0];
        float z  = agentF[3 * row + 1];
        float pz = agentF[3 * row + 2];
        float2 g = goal2[row];

        int c = bucket_index(x, z, pz, g.x, g.y);
        out[row] = sLS[c];
    }
}

extern "C" void kernel_launch(void* const* d_in, const int* in_sizes, int n_in,
                              void* d_out, int out_size) {
    const float* agent = (const float*)d_in[0];   // [B,3]
    const float* goal = (const float*)d_in[1];    // [B,2]
    const float* radius_table = (const float*)d_in[2];
    const float* angle_table = (const float*)d_in[3];
    const float* W = (const float*)d_in[4];
    const float* b = (const float*)d_in[5];

    int n = in_sizes[0] / 3;    // B = 2,000,000

    int tiles = (n + TPB - 1) / TPB;
    int blocks = 148 * 8;       // persistent: amortize prologue, ~6.6 iters
    if (blocks > tiles) blocks = tiles;

    goal_position_fused<<<blocks, TPB>>>(agent,
                                         (const float2*)goal,
                                         (float4*)d_out, n,
                                         radius_table, angle_table, W, b);
}